// round 1
// baseline (speedup 1.0000x reference)
#include <cuda_runtime.h>

#define HWSZ 36864   // 192*192
#define WIMG 192

__global__ void zero_out_kernel(float* __restrict__ out, int n4) {
    int i = blockIdx.x * blockDim.x + threadIdx.x;
    if (i < n4) reinterpret_cast<float4*>(out)[i] = make_float4(0.f, 0.f, 0.f, 0.f);
}

__global__ __launch_bounds__(64) void wdwa_attn_kernel(
    const float* __restrict__ x,    // (576, 192, 192)
    const float* __restrict__ fc,   // (8, 8, 2) cos/sin
    const float* __restrict__ wgt,  // (192, 192)
    float* __restrict__ out)        // (192, 192, 192)
{
    __shared__ float Ks[64][24];
    __shared__ float Vs[64][24];
    __shared__ float cs[64], sn[64];   // [pos*8 + t]

    const int wi   = blockIdx.x;     // 0..1023  = ih*64 + iw*4 + g
    const int head = blockIdx.y;     // 0..7
    const int tid  = threadIdx.x;    // 0..63 = query pixel y*8+x

    const int ih = wi >> 6;
    const int rem = wi & 63;
    const int iw = rem >> 2;
    const int g  = rem & 3;
    const int rshift = (g & 1) ? 6 : 0;
    const int cshift = (g & 2) ? 6 : 0;

    cs[tid] = fc[2 * tid];
    sn[tid] = fc[2 * tid + 1];

    const int y  = tid >> 3;
    const int xx = tid & 7;

    // source pixel in x (reflect map for shifted copies)
    int sr = ih * 12 + y;
    if (rshift) sr = (sr < 186) ? sr + 6 : 376 - sr;
    int sc = iw * 12 + xx;
    if (cshift) sc = (sc < 186) ? sc + 6 : 376 - sc;

    const float* xp = x + sr * WIMG + sc;
    const int qb = head * 24;
    const int kb = 192 + head * 24;
    const int vb = 384 + head * 24;

    float q[24], kv[24];
#pragma unroll
    for (int c = 0; c < 24; c++) q[c]  = xp[(qb + c) * HWSZ];
#pragma unroll
    for (int c = 0; c < 24; c++) kv[c] = xp[(kb + c) * HWSZ];

    __syncthreads();  // cs/sn ready

    // hs_pe helix rotation on q and k (per triple t)
#pragma unroll
    for (int t = 0; t < 8; t++) {
        const float cy = cs[y * 8 + t],  sy = sn[y * 8 + t];
        const float cx = cs[xx * 8 + t], sx = sn[xx * 8 + t];
        {
            float a = q[3*t], b = q[3*t+1], c2 = q[3*t+2];
            float a2 = a * cy - b * sy;
            float b2 = a * sy + b * cy;
            q[3*t]   = a2;
            q[3*t+1] = b2 * cx - c2 * sx;
            q[3*t+2] = b2 * sx + c2 * cx;
        }
        {
            float a = kv[3*t], b = kv[3*t+1], c2 = kv[3*t+2];
            float a2 = a * cy - b * sy;
            float b2 = a * sy + b * cy;
            kv[3*t]   = a2;
            kv[3*t+1] = b2 * cx - c2 * sx;
            kv[3*t+2] = b2 * sx + c2 * cx;
        }
    }

#pragma unroll
    for (int c = 0; c < 24; c++) Ks[tid][c] = kv[c];
#pragma unroll
    for (int c = 0; c < 24; c++) Vs[tid][c] = xp[(vb + c) * HWSZ];

    __syncthreads();

    const float scale = 0.20412414523193154f;  // 1/sqrt(24)

    // scores (thread owns one query row)
    float s[64];
    float m = -1e30f;
#pragma unroll
    for (int j = 0; j < 64; j++) {
        const float4* kr = reinterpret_cast<const float4*>(Ks[j]);
        float d = 0.f;
#pragma unroll
        for (int c = 0; c < 6; c++) {
            float4 k4 = kr[c];
            d += q[4*c]   * k4.x;
            d += q[4*c+1] * k4.y;
            d += q[4*c+2] * k4.z;
            d += q[4*c+3] * k4.w;
        }
        d *= scale;
        s[j] = d;
        m = fmaxf(m, d);
    }

    // softmax + weighted V accumulation
    float den = 0.f;
    float o[24];
#pragma unroll
    for (int c = 0; c < 24; c++) o[c] = 0.f;
#pragma unroll
    for (int j = 0; j < 64; j++) {
        const float e = __expf(s[j] - m);
        den += e;
        const float4* vr = reinterpret_cast<const float4*>(Vs[j]);
#pragma unroll
        for (int c = 0; c < 6; c++) {
            float4 v4 = vr[c];
            o[4*c]   += e * v4.x;
            o[4*c+1] += e * v4.y;
            o[4*c+2] += e * v4.z;
            o[4*c+3] += e * v4.w;
        }
    }
    const float inv = 1.0f / den;

    // reverse scatter: g-layer shift, crop, fold in 1/weight
    const int gr = ih * 12 + y + rshift;
    const int gc = iw * 12 + xx + cshift;
    if (gr < 192 && gc < 192) {
        const float wv = inv / wgt[gr * WIMG + gc];
        float* op = out + head * 24 * HWSZ + gr * WIMG + gc;
#pragma unroll
        for (int c = 0; c < 24; c++) atomicAdd(op + c * HWSZ, o[c] * wv);
    }
}

extern "C" void kernel_launch(void* const* d_in, const int* in_sizes, int n_in,
                              void* d_out, int out_size) {
    const float* x   = (const float*)d_in[0];
    const float* fc  = (const float*)d_in[1];
    const float* wgt = (const float*)d_in[2];
    float* out = (float*)d_out;

    const int n4 = (192 * 36864) / 4;  // 1769472 float4s
    zero_out_kernel<<<(n4 + 255) / 256, 256>>>(out, n4);

    dim3 grid(1024, 8);
    wdwa_attn_kernel<<<grid, 64>>>(x, fc, wgt, out);
}

// round 3
// speedup vs baseline: 1.0137x; 1.0137x over previous
#include <cuda_runtime.h>

#define HWSZ 36864   // 192*192
#define WIMG 192

typedef unsigned long long u64;

__device__ __forceinline__ u64 pack2(float lo, float hi) {
    u64 r;
    asm("mov.b64 %0, {%1, %2};" : "=l"(r) : "f"(lo), "f"(hi));
    return r;
}
__device__ __forceinline__ void unpack2(u64 v, float& lo, float& hi) {
    asm("mov.b64 {%0, %1}, %2;" : "=f"(lo), "=f"(hi) : "l"(v));
}
__device__ __forceinline__ u64 ffma2(u64 a, u64 b, u64 c) {
    u64 d;
    asm("fma.rn.f32x2 %0, %1, %2, %3;" : "=l"(d) : "l"(a), "l"(b), "l"(c));
    return d;
}

__global__ void zero_out_kernel(float* __restrict__ out, int n4) {
    int i = blockIdx.x * blockDim.x + threadIdx.x;
    if (i < n4) reinterpret_cast<float4*>(out)[i] = make_float4(0.f, 0.f, 0.f, 0.f);
}

__global__ __launch_bounds__(64) void wdwa_attn_kernel(
    const float* __restrict__ x,    // (576, 192, 192)
    const float* __restrict__ fc,   // (8, 8, 2) cos/sin
    const float* __restrict__ wgt,  // (192, 192)
    float* __restrict__ out)        // (192, 192, 192)
{
    __shared__ __align__(16) float Ks[64][24];
    __shared__ __align__(16) float Vs[64][24];
    __shared__ float cs[64], sn[64];   // [pos*8 + t]

    const int wi   = blockIdx.x;     // 0..1023  = ih*64 + iw*4 + g
    const int head = blockIdx.y;     // 0..7
    const int tid  = threadIdx.x;    // 0..63 = query pixel y*8+x

    const int ih = wi >> 6;
    const int rem = wi & 63;
    const int iw = rem >> 2;
    const int g  = rem & 3;
    const int rshift = (g & 1) ? 6 : 0;
    const int cshift = (g & 2) ? 6 : 0;

    cs[tid] = fc[2 * tid];
    sn[tid] = fc[2 * tid + 1];

    const int y  = tid >> 3;
    const int xx = tid & 7;

    // source pixel in x (reflect map for shifted copies)
    int sr = ih * 12 + y;
    if (rshift) sr = (sr < 186) ? sr + 6 : 376 - sr;
    int sc = iw * 12 + xx;
    if (cshift) sc = (sc < 186) ? sc + 6 : 376 - sc;

    const float* xp = x + sr * WIMG + sc;
    const int qb = head * 24;
    const int kb = 192 + head * 24;
    const int vb = 384 + head * 24;

    float q[24], kv[24];
#pragma unroll
    for (int c = 0; c < 24; c++) q[c]  = xp[(qb + c) * HWSZ];
#pragma unroll
    for (int c = 0; c < 24; c++) kv[c] = xp[(kb + c) * HWSZ];

    __syncthreads();  // cs/sn ready

    // hs_pe helix rotation on q and k (per triple t)
#pragma unroll
    for (int t = 0; t < 8; t++) {
        const float cy = cs[y * 8 + t],  sy = sn[y * 8 + t];
        const float cx = cs[xx * 8 + t], sx = sn[xx * 8 + t];
        {
            float a = q[3*t], b = q[3*t+1], c2 = q[3*t+2];
            float a2 = a * cy - b * sy;
            float b2 = a * sy + b * cy;
            q[3*t]   = a2;
            q[3*t+1] = b2 * cx - c2 * sx;
            q[3*t+2] = b2 * sx + c2 * cx;
        }
        {
            float a = kv[3*t], b = kv[3*t+1], c2 = kv[3*t+2];
            float a2 = a * cy - b * sy;
            float b2 = a * sy + b * cy;
            kv[3*t]   = a2;
            kv[3*t+1] = b2 * cx - c2 * sx;
            kv[3*t+2] = b2 * sx + c2 * cx;
        }
    }

#pragma unroll
    for (int c = 0; c < 24; c++) Ks[tid][c] = kv[c];
#pragma unroll
    for (int c = 0; c < 24; c++) Vs[tid][c] = xp[(vb + c) * HWSZ];

    // Pre-scale q by 1/sqrt(24) (folds the score scaling), pack into f32x2
    const float scale = 0.20412414523193154f;  // 1/sqrt(24)
    u64 qp[12];
#pragma unroll
    for (int c = 0; c < 12; c++) qp[c] = pack2(q[2*c] * scale, q[2*c+1] * scale);

    __syncthreads();

    // ---- scores: s[j] = <q_scaled, K[j]>  via packed FFMA2 ----
    float s[64];
    float m = -1e30f;
#pragma unroll
    for (int j = 0; j < 64; j++) {
        const ulonglong2* kr = reinterpret_cast<const ulonglong2*>(Ks[j]);
        u64 acc0 = 0ull, acc1 = 0ull;
#pragma unroll
        for (int c = 0; c < 6; c++) {
            ulonglong2 kk = kr[c];
            acc0 = ffma2(qp[2*c],   kk.x, acc0);
            acc1 = ffma2(qp[2*c+1], kk.y, acc1);
        }
        float a0, a1, b0, b1;
        unpack2(acc0, a0, a1);
        unpack2(acc1, b0, b1);
        const float d = (a0 + a1) + (b0 + b1);
        s[j] = d;
        m = fmaxf(m, d);
    }

    // ---- softmax + PV accumulation via packed FFMA2 ----
    const float L2E = 1.4426950408889634f;
    const float mb = m * L2E;
    float den = 0.f;
    u64 op[12];
#pragma unroll
    for (int c = 0; c < 12; c++) op[c] = 0ull;
#pragma unroll
    for (int j = 0; j < 64; j++) {
        const float e = exp2f(fmaf(s[j], L2E, -mb));
        den += e;
        const u64 ee = pack2(e, e);
        const ulonglong2* vr = reinterpret_cast<const ulonglong2*>(Vs[j]);
#pragma unroll
        for (int c = 0; c < 6; c++) {
            ulonglong2 vv = vr[c];
            op[2*c]   = ffma2(ee, vv.x, op[2*c]);
            op[2*c+1] = ffma2(ee, vv.y, op[2*c+1]);
        }
    }
    const float inv = 1.0f / den;

    // reverse scatter: g-layer shift, crop, fold in 1/weight
    const int gr = ih * 12 + y + rshift;
    const int gc = iw * 12 + xx + cshift;
    if (gr < 192 && gc < 192) {
        const float wv = inv / wgt[gr * WIMG + gc];
        float* optr = out + head * 24 * HWSZ + gr * WIMG + gc;
#pragma unroll
        for (int c = 0; c < 12; c++) {
            float o0, o1;
            unpack2(op[c], o0, o1);
            atomicAdd(optr + (2*c)   * HWSZ, o0 * wv);
            atomicAdd(optr + (2*c+1) * HWSZ, o1 * wv);
        }
    }
}

extern "C" void kernel_launch(void* const* d_in, const int* in_sizes, int n_in,
                              void* d_out, int out_size) {
    const float* x   = (const float*)d_in[0];
    const float* fc  = (const float*)d_in[1];
    const float* wgt = (const float*)d_in[2];
    float* out = (float*)d_out;

    const int n4 = (192 * 36864) / 4;  // 1769472 float4s
    zero_out_kernel<<<(n4 + 255) / 256, 256>>>(out, n4);

    dim3 grid(1024, 8);
    wdwa_attn_kernel<<<grid, 64>>>(x, fc, wgt, out);
}

// round 6
// speedup vs baseline: 1.1345x; 1.1191x over previous
#include <cuda_runtime.h>

#define HWSZ 36864   // 192*192
#define WIMG 192

typedef unsigned long long u64;

__device__ __forceinline__ u64 pack2(float lo, float hi) {
    u64 r;
    asm("mov.b64 %0, {%1, %2};" : "=l"(r) : "f"(lo), "f"(hi));
    return r;
}
__device__ __forceinline__ void unpack2(u64 v, float& lo, float& hi) {
    asm("mov.b64 {%0, %1}, %2;" : "=f"(lo), "=f"(hi) : "l"(v));
}
__device__ __forceinline__ u64 ffma2(u64 a, u64 b, u64 c) {
    u64 d;
    asm("fma.rn.f32x2 %0, %1, %2, %3;" : "=l"(d) : "l"(a), "l"(b), "l"(c));
    return d;
}
__device__ __forceinline__ u64 fmul2(u64 a, u64 b) {
    u64 d;
    asm("mul.rn.f32x2 %0, %1, %2;" : "=l"(d) : "l"(a), "l"(b));
    return d;
}
__device__ __forceinline__ float ex2(float a) {
    float r;
    asm("ex2.approx.ftz.f32 %0, %1;" : "=f"(r) : "f"(a));
    return r;
}

__global__ void zero_out_kernel(float* __restrict__ out, int n4) {
    int i = blockIdx.x * blockDim.x + threadIdx.x;
    if (i < n4) reinterpret_cast<float4*>(out)[i] = make_float4(0.f, 0.f, 0.f, 0.f);
}

// One warp per (window, head); each thread owns 2 query pixels (l, l+32).
__global__ __launch_bounds__(32, 12) void wdwa_attn_kernel(
    const float* __restrict__ x,    // (576, 192, 192)
    const float* __restrict__ fc,   // (8, 8, 2) cos/sin
    const float* __restrict__ wgt,  // (192, 192)
    float* __restrict__ out)        // (192, 192, 192)
{
    __shared__ __align__(16) float Ks[64][24];
    __shared__ __align__(16) float Vs[64][24];
    __shared__ float cs[64], sn[64];   // [pos*8 + t]

    const int wi   = blockIdx.x;     // 0..1023 = ih*64 + iw*4 + g
    const int head = blockIdx.y;     // 0..7
    const int l    = threadIdx.x;    // 0..31

    const int ih = wi >> 6;
    const int rem = wi & 63;
    const int iw = rem >> 2;
    const int g  = rem & 3;
    const int rshift = (g & 1) ? 6 : 0;
    const int cshift = (g & 2) ? 6 : 0;

    cs[l]      = fc[2 * l];
    sn[l]      = fc[2 * l + 1];
    cs[l + 32] = fc[2 * (l + 32)];
    sn[l + 32] = fc[2 * (l + 32) + 1];
    __syncwarp();

    const int qb = head * 24;
    const int kb = 192 + head * 24;
    const int vb = 384 + head * 24;

    // folded: 1/sqrt(24) * log2(e)
    const float QSCALE = 0.20412414523193154f * 1.4426950408889634f;

    u64 qp[2][12];
    int grr[2], gcc[2];

#pragma unroll
    for (int pix = 0; pix < 2; pix++) {
        const int p  = l + 32 * pix;
        const int y  = p >> 3;
        const int xx = p & 7;

        int sr = ih * 12 + y;
        if (rshift) sr = (sr < 186) ? sr + 6 : 376 - sr;
        int sc = iw * 12 + xx;
        if (cshift) sc = (sc < 186) ? sc + 6 : 376 - sc;

        grr[pix] = ih * 12 + y + rshift;
        gcc[pix] = iw * 12 + xx + cshift;

        const float* xp = x + sr * WIMG + sc;

        float q[24], kv[24];
#pragma unroll
        for (int c = 0; c < 24; c++) q[c]  = xp[(qb + c) * HWSZ];
#pragma unroll
        for (int c = 0; c < 24; c++) kv[c] = xp[(kb + c) * HWSZ];
#pragma unroll
        for (int c = 0; c < 24; c++) Vs[p][c] = xp[(vb + c) * HWSZ];

        // hs_pe rotation on q and k
#pragma unroll
        for (int t = 0; t < 8; t++) {
            const float cy = cs[y * 8 + t],  sy = sn[y * 8 + t];
            const float cx = cs[xx * 8 + t], sx = sn[xx * 8 + t];
            {
                float a = q[3*t], b = q[3*t+1], c2 = q[3*t+2];
                float a2 = a * cy - b * sy;
                float b2 = a * sy + b * cy;
                q[3*t]   = a2;
                q[3*t+1] = b2 * cx - c2 * sx;
                q[3*t+2] = b2 * sx + c2 * cx;
            }
            {
                float a = kv[3*t], b = kv[3*t+1], c2 = kv[3*t+2];
                float a2 = a * cy - b * sy;
                float b2 = a * sy + b * cy;
                kv[3*t]   = a2;
                kv[3*t+1] = b2 * cx - c2 * sx;
                kv[3*t+2] = b2 * sx + c2 * cx;
            }
        }

#pragma unroll
        for (int c = 0; c < 24; c++) Ks[p][c] = kv[c];

#pragma unroll
        for (int c = 0; c < 12; c++) qp[pix][c] = pack2(q[2*c] * QSCALE, q[2*c+1] * QSCALE);
    }

    __syncwarp();

    // ---- tiled online softmax-attention (exact), tile = 8 keys ----
    float m0 = -1e30f, m1 = -1e30f;
    float den0 = 0.f, den1 = 0.f;
    u64 o0[12], o1[12];
#pragma unroll
    for (int c = 0; c < 12; c++) { o0[c] = 0ull; o1[c] = 0ull; }

#pragma unroll
    for (int t = 0; t < 8; t++) {
        float st0[8], st1[8];
        float tm0 = -1e30f, tm1 = -1e30f;
#pragma unroll
        for (int jj = 0; jj < 8; jj++) {
            const int j = t * 8 + jj;
            const ulonglong2* kr = reinterpret_cast<const ulonglong2*>(Ks[j]);
            u64 a0 = 0ull, a1 = 0ull, b0 = 0ull, b1 = 0ull;
#pragma unroll
            for (int c = 0; c < 6; c++) {
                ulonglong2 kk = kr[c];
                a0 = ffma2(qp[0][2*c],   kk.x, a0);
                a1 = ffma2(qp[0][2*c+1], kk.y, a1);
                b0 = ffma2(qp[1][2*c],   kk.x, b0);
                b1 = ffma2(qp[1][2*c+1], kk.y, b1);
            }
            float x0, x1, x2, x3;
            unpack2(a0, x0, x1); unpack2(a1, x2, x3);
            const float d0 = (x0 + x1) + (x2 + x3);
            unpack2(b0, x0, x1); unpack2(b1, x2, x3);
            const float d1 = (x0 + x1) + (x2 + x3);
            st0[jj] = d0; tm0 = fmaxf(tm0, d0);
            st1[jj] = d1; tm1 = fmaxf(tm1, d1);
        }

        const float n0 = fmaxf(m0, tm0);
        const float n1 = fmaxf(m1, tm1);
        const float f0 = ex2(m0 - n0);   // 0 on first tile (underflow)
        const float f1 = ex2(m1 - n1);
        den0 *= f0; den1 *= f1;
        const u64 ff0 = pack2(f0, f0), ff1 = pack2(f1, f1);
#pragma unroll
        for (int c = 0; c < 12; c++) { o0[c] = fmul2(o0[c], ff0); o1[c] = fmul2(o1[c], ff1); }
        m0 = n0; m1 = n1;

#pragma unroll
        for (int jj = 0; jj < 8; jj++) {
            const int j = t * 8 + jj;
            const float e0 = ex2(st0[jj] - m0);
            const float e1 = ex2(st1[jj] - m1);
            den0 += e0; den1 += e1;
            const u64 ee0 = pack2(e0, e0), ee1 = pack2(e1, e1);
            const ulonglong2* vr = reinterpret_cast<const ulonglong2*>(Vs[j]);
#pragma unroll
            for (int c = 0; c < 6; c++) {
                ulonglong2 vv = vr[c];
                o0[2*c]   = ffma2(ee0, vv.x, o0[2*c]);
                o0[2*c+1] = ffma2(ee0, vv.y, o0[2*c+1]);
                o1[2*c]   = ffma2(ee1, vv.x, o1[2*c]);
                o1[2*c+1] = ffma2(ee1, vv.y, o1[2*c+1]);
            }
        }
    }

    const float inv0 = 1.0f / den0;
    const float inv1 = 1.0f / den1;

    // reverse scatter: g-layer shift, crop, fold in 1/weight
#pragma unroll
    for (int pix = 0; pix < 2; pix++) {
        const int gr = grr[pix];
        const int gc = gcc[pix];
        if (gr < 192 && gc < 192) {
            const float wv = (pix ? inv1 : inv0) / wgt[gr * WIMG + gc];
            float* optr = out + head * 24 * HWSZ + gr * WIMG + gc;
            const u64* op = pix ? o1 : o0;
#pragma unroll
            for (int c = 0; c < 12; c++) {
                float v0, v1;
                unpack2(op[c], v0, v1);
                atomicAdd(optr + (2*c)   * HWSZ, v0 * wv);
                atomicAdd(optr + (2*c+1) * HWSZ, v1 * wv);
            }
        }
    }
}

extern "C" void kernel_launch(void* const* d_in, const int* in_sizes, int n_in,
                              void* d_out, int out_size) {
    const float* x   = (const float*)d_in[0];
    const float* fc  = (const float*)d_in[1];
    const float* wgt = (const float*)d_in[2];
    float* out = (float*)d_out;

    const int n4 = (192 * 36864) / 4;
    zero_out_kernel<<<(n4 + 255) / 256, 256>>>(out, n4);

    dim3 grid(1024, 8);
    wdwa_attn_kernel<<<grid, 32>>>(x, fc, wgt, out);
}